// round 2
// baseline (speedup 1.0000x reference)
#include <cuda_runtime.h>

#define D          128
#define DV         (D / 4)        // 32 float4 per row
#define NWARPS     8
#define NTHREADS   256
#define CACHE_ROWS 208            // 208 rows * 512B = 104KB dynamic smem cache
#define CACHE_BYTES (CACHE_ROWS * 64 * 8)   // 208*512 = 106496 B
#define MAXB       16384
#define TR         32             // GEMM row tile

// Scratch (allocation-free per harness rules)
__device__ int   g_seg_start[MAXB + 1];
__device__ float g_pooled[(size_t)MAXB * D];

// ---------------------------------------------------------------------------
// Kernel 0: segment boundaries via adjacent-diff scan (batch sorted ascending).
// seg_start[v] = first i with batch[i] >= v.  Thread i: if batch[i-1] < v <=
// batch[i] then seg_start[v] = i (loop covers empty segments). Thread N does
// the tail. Coalesced streaming read instead of dependent binary searches.
// ---------------------------------------------------------------------------
__global__ void seg_bounds_scan(const int* __restrict__ batch, int N, int B)
{
    int i = blockIdx.x * blockDim.x + threadIdx.x;
    if (i > N) return;
    if (i == N) {                       // v in (batch[N-1], B] -> N
        int last = batch[N - 1];
        for (int v = last + 1; v <= B; v++) g_seg_start[v] = N;
        return;
    }
    int cur  = batch[i];
    int prev = (i == 0) ? -1 : batch[i - 1];
    for (int v = prev + 1; v <= cur; v++) g_seg_start[v] = i;
}

// ---------------------------------------------------------------------------
// Kernel 1: per-segment attention pooling. One CTA per segment.
// Pass 1: column sums -> coarse, caching first CACHE_ROWS rows in smem.
// Pass 2: att_i = <x_i, coarse>; accumulate x_i*att_i (85% smem, rest L2).
// 104KB dynamic smem -> 2 CTAs/SM -> 37MB concurrent footprint (L2-resident).
// ---------------------------------------------------------------------------
__global__ void __launch_bounds__(NTHREADS)
attention_pool_kernel(const float4* __restrict__ x)
{
    extern __shared__ float4 s_cache[];            // CACHE_ROWS * DV
    __shared__ float4 s_partial[NWARPS][DV];       // 4KB
    __shared__ float4 s_coarse[DV];                // 512B

    const int b     = blockIdx.x;
    const int start = g_seg_start[b];
    const int end   = g_seg_start[b + 1];
    const int cnt   = end - start;
    const float inv = 1.0f / (float)(cnt > 0 ? cnt : 1);
    const int w     = threadIdx.x >> 5;
    const int lane  = threadIdx.x & 31;

    // ---- Pass 1: column sums, 8-row load batches for MLP ----
    float4 s = make_float4(0.f, 0.f, 0.f, 0.f);
    int r = start + w;
    for (; r + 7 * NWARPS < end; r += 8 * NWARPS) {
        float4 v[8];
#pragma unroll
        for (int k = 0; k < 8; k++)
            v[k] = x[(size_t)(r + k * NWARPS) * DV + lane];
#pragma unroll
        for (int k = 0; k < 8; k++) {
            int c = (r - start) + k * NWARPS;
            if (c < CACHE_ROWS) s_cache[c * DV + lane] = v[k];
            s.x += v[k].x; s.y += v[k].y; s.z += v[k].z; s.w += v[k].w;
        }
    }
    for (; r < end; r += NWARPS) {
        float4 v = x[(size_t)r * DV + lane];
        int c = r - start;
        if (c < CACHE_ROWS) s_cache[c * DV + lane] = v;
        s.x += v.x; s.y += v.y; s.z += v.z; s.w += v.w;
    }
    s_partial[w][lane] = s;
    __syncthreads();
    if (threadIdx.x < 32) {
        float4 c = s_partial[0][lane];
#pragma unroll
        for (int i = 1; i < NWARPS; i++) {
            float4 t = s_partial[i][lane];
            c.x += t.x; c.y += t.y; c.z += t.z; c.w += t.w;
        }
        c.x *= inv; c.y *= inv; c.z *= inv; c.w *= inv;
        s_coarse[lane] = c;
    }
    __syncthreads();
    const float4 cf = s_coarse[lane];

    // ---- Pass 2: att + scaled accumulation, unroll 4 ----
    float4 acc = make_float4(0.f, 0.f, 0.f, 0.f);
    r = start + w;
    for (; r + 3 * NWARPS < end; r += 4 * NWARPS) {
        float4 v[4];
        float  d[4];
#pragma unroll
        for (int k = 0; k < 4; k++) {
            int c = (r - start) + k * NWARPS;
            v[k] = (c < CACHE_ROWS) ? s_cache[c * DV + lane]
                                    : x[(size_t)(r + k * NWARPS) * DV + lane];
            d[k] = v[k].x * cf.x + v[k].y * cf.y + v[k].z * cf.z + v[k].w * cf.w;
        }
#pragma unroll
        for (int o = 16; o > 0; o >>= 1) {
#pragma unroll
            for (int k = 0; k < 4; k++)
                d[k] += __shfl_xor_sync(0xffffffffu, d[k], o);
        }
#pragma unroll
        for (int k = 0; k < 4; k++) {
            acc.x += v[k].x * d[k];
            acc.y += v[k].y * d[k];
            acc.z += v[k].z * d[k];
            acc.w += v[k].w * d[k];
        }
    }
    for (; r < end; r += NWARPS) {
        int c = r - start;
        float4 v = (c < CACHE_ROWS) ? s_cache[c * DV + lane]
                                    : x[(size_t)r * DV + lane];
        float d = v.x * cf.x + v.y * cf.y + v.z * cf.z + v.w * cf.w;
#pragma unroll
        for (int o = 16; o > 0; o >>= 1)
            d += __shfl_xor_sync(0xffffffffu, d, o);
        acc.x += v.x * d; acc.y += v.y * d; acc.z += v.z * d; acc.w += v.w * d;
    }
    s_partial[w][lane] = acc;
    __syncthreads();
    if (threadIdx.x < 32) {
        float4 p = s_partial[0][lane];
#pragma unroll
        for (int i = 1; i < NWARPS; i++) {
            float4 t = s_partial[i][lane];
            p.x += t.x; p.y += t.y; p.z += t.z; p.w += t.w;
        }
        p.x *= inv; p.y *= inv; p.z *= inv; p.w *= inv;
        ((float4*)g_pooled)[(size_t)b * DV + lane] = p;
    }
}

// ---------------------------------------------------------------------------
// Kernel 2: out[B,128] = pooled[B,128] @ W^T + bias.
// ---------------------------------------------------------------------------
__global__ void __launch_bounds__(128)
out_gemm_kernel(const float* __restrict__ W, const float* __restrict__ bias,
                float* __restrict__ out, int B)
{
    __shared__ float sp[TR][D];   // 16KB
    const int rb = blockIdx.x * TR;
    int rows = B - rb; if (rows > TR) rows = TR;

    const float4* src = (const float4*)(g_pooled + (size_t)rb * D);
    float4* dst = (float4*)sp;
    for (int i = threadIdx.x; i < rows * DV; i += 128) dst[i] = src[i];
    __syncthreads();

    const int j = threadIdx.x;            // output column
    float acc[TR];
    const float bj = bias[j];
#pragma unroll
    for (int r2 = 0; r2 < TR; r2++) acc[r2] = bj;

    const float4* W4  = (const float4*)(W + (size_t)j * D);
    const float4* sp4 = (const float4*)sp;
    for (int k = 0; k < DV; k++) {
        float4 wv = W4[k];
#pragma unroll
        for (int r2 = 0; r2 < TR; r2++) {
            float4 pv = sp4[r2 * DV + k];
            acc[r2] += pv.x * wv.x + pv.y * wv.y + pv.z * wv.z + pv.w * wv.w;
        }
    }
    for (int r2 = 0; r2 < rows; r2++)
        out[(size_t)(rb + r2) * D + j] = acc[r2];
}

// ---------------------------------------------------------------------------
extern "C" void kernel_launch(void* const* d_in, const int* in_sizes, int n_in,
                              void* d_out, int out_size)
{
    const float* x     = (const float*)d_in[0];
    const int*   batch = (const int*)  d_in[1];
    const float* W     = (const float*)d_in[2];
    const float* bias  = (const float*)d_in[3];
    (void)n_in;

    const int N = in_sizes[1];        // number of rows
    const int B = out_size / D;       // number of segments

    static bool attr_done = false;
    if (!attr_done) {
        cudaFuncSetAttribute(attention_pool_kernel,
                             cudaFuncAttributeMaxDynamicSharedMemorySize,
                             CACHE_BYTES);
        attr_done = true;
    }

    int sblocks = (N + 1 + 255) / 256;
    seg_bounds_scan<<<sblocks, 256>>>(batch, N, B);
    attention_pool_kernel<<<B, NTHREADS, CACHE_BYTES>>>((const float4*)x);
    out_gemm_kernel<<<(B + TR - 1) / TR, 128>>>(W, bias, (float*)d_out, B);
}

// round 4
// speedup vs baseline: 1.2697x; 1.2697x over previous
#include <cuda_runtime.h>

#define D          128
#define DV         (D / 4)      // 32 float4 per row
#define NWARPS     8
#define NTHREADS   256
#define CACHE_ROWS 80           // 80 rows * 512B = 40KB static smem cache
#define MAXB       16384
#define TR         32           // GEMM row tile

// Scratch (allocation-free per harness rules)
__device__ int   g_seg_start[MAXB + 1];
__device__ float g_pooled[(size_t)MAXB * D];

// ---- L2 eviction-policy hinted float4 loads (createpolicy + cache_hint) ----
__device__ __forceinline__ unsigned long long mk_policy_evict_last() {
    unsigned long long p;
    asm("createpolicy.fractional.L2::evict_last.b64 %0, 1.0;" : "=l"(p));
    return p;
}
__device__ __forceinline__ unsigned long long mk_policy_evict_first() {
    unsigned long long p;
    asm("createpolicy.fractional.L2::evict_first.b64 %0, 1.0;" : "=l"(p));
    return p;
}
__device__ __forceinline__ float4 ldg_hint(const float4* p, unsigned long long pol) {
    float4 v;
    asm volatile("ld.global.nc.L2::cache_hint.v4.f32 {%0,%1,%2,%3}, [%4], %5;"
                 : "=f"(v.x), "=f"(v.y), "=f"(v.z), "=f"(v.w)
                 : "l"(p), "l"(pol));
    return v;
}

// ---------------------------------------------------------------------------
// Kernel 0: segment boundaries, vectorized adjacent-diff scan.
// Thread t handles elements [4t, 4t+4). seg_start[v] = first i, batch[i] >= v.
// ---------------------------------------------------------------------------
__global__ void seg_bounds_scan(const int4* __restrict__ batch4,
                                const int*  __restrict__ batch, int N, int B)
{
    int t  = blockIdx.x * blockDim.x + threadIdx.x;
    int i  = t * 4;
    int nt = (N + 3) / 4;                        // vector threads
    if (t > nt) return;
    if (t == nt) {                               // tail: (batch[N-1], B] -> N
        int last = batch[N - 1];
        for (int v = last + 1; v <= B; v++) g_seg_start[v] = N;
        return;
    }
    int prev = (i == 0) ? -1 : batch[i - 1];
    if (i + 3 < N) {
        int4 c = batch4[t];
        int vals[4] = {c.x, c.y, c.z, c.w};
#pragma unroll
        for (int k = 0; k < 4; k++) {
            for (int v = prev + 1; v <= vals[k]; v++) g_seg_start[v] = i + k;
            prev = vals[k];
        }
    } else {
        for (int k = 0; k < 4 && i + k < N; k++) {
            int cur = batch[i + k];
            for (int v = prev + 1; v <= cur; v++) g_seg_start[v] = i + k;
            prev = cur;
        }
    }
}

// ---------------------------------------------------------------------------
// Kernel 1: per-segment attention pooling. One CTA per segment (R1 config:
// 40KB static cache -> 5 CTAs/SM, ~740 concurrent segments).
// Pass 1: column sums -> coarse; first 80 rows cached in smem; uncached rows
//         loaded with L2 evict_last policy so they survive until pass 2.
// Pass 2: att_i = <x_i, coarse>; accumulate x_i*att_i; uncached rows read
//         with evict_first policy (dead after use).
// ---------------------------------------------------------------------------
__global__ void __launch_bounds__(NTHREADS)
attention_pool_kernel(const float4* __restrict__ x)
{
    __shared__ float4 s_partial[NWARPS][DV];     // 4KB
    __shared__ float4 s_coarse[DV];              // 512B
    __shared__ float4 s_cache[CACHE_ROWS * DV];  // 40KB

    const int b     = blockIdx.x;
    const int start = g_seg_start[b];
    const int end   = g_seg_start[b + 1];
    const int cnt   = end - start;
    const float inv = 1.0f / (float)(cnt > 0 ? cnt : 1);
    const int w     = threadIdx.x >> 5;
    const int lane  = threadIdx.x & 31;

    const unsigned long long pol_last  = mk_policy_evict_last();
    const unsigned long long pol_first = mk_policy_evict_first();

    // ---- Pass 1: column sums ----
    float4 s = make_float4(0.f, 0.f, 0.f, 0.f);
    int r = start + w;
    for (; r + 3 * NWARPS < end; r += 4 * NWARPS) {
        float4 v[4];
#pragma unroll
        for (int k = 0; k < 4; k++) {
            int c = (r - start) + k * NWARPS;
            const float4* p = &x[(size_t)(r + k * NWARPS) * DV + lane];
            v[k] = (c < CACHE_ROWS) ? *p : ldg_hint(p, pol_last);
        }
#pragma unroll
        for (int k = 0; k < 4; k++) {
            int c = (r - start) + k * NWARPS;
            if (c < CACHE_ROWS) s_cache[c * DV + lane] = v[k];
            s.x += v[k].x; s.y += v[k].y; s.z += v[k].z; s.w += v[k].w;
        }
    }
    for (; r < end; r += NWARPS) {
        int c = r - start;
        const float4* p = &x[(size_t)r * DV + lane];
        float4 v = (c < CACHE_ROWS) ? *p : ldg_hint(p, pol_last);
        if (c < CACHE_ROWS) s_cache[c * DV + lane] = v;
        s.x += v.x; s.y += v.y; s.z += v.z; s.w += v.w;
    }
    s_partial[w][lane] = s;
    __syncthreads();
    if (threadIdx.x < 32) {
        float4 c = s_partial[0][lane];
#pragma unroll
        for (int i = 1; i < NWARPS; i++) {
            float4 t = s_partial[i][lane];
            c.x += t.x; c.y += t.y; c.z += t.z; c.w += t.w;
        }
        c.x *= inv; c.y *= inv; c.z *= inv; c.w *= inv;
        s_coarse[lane] = c;
    }
    __syncthreads();
    const float4 cf = s_coarse[lane];

    // ---- Pass 2: att + scaled accumulation ----
    float4 acc = make_float4(0.f, 0.f, 0.f, 0.f);
    r = start + w;
    for (; r + NWARPS < end; r += 2 * NWARPS) {
        int c0 = r - start;
        int c1 = c0 + NWARPS;
        float4 v0 = (c0 < CACHE_ROWS) ? s_cache[c0 * DV + lane]
                                      : ldg_hint(&x[(size_t)r * DV + lane], pol_first);
        float4 v1 = (c1 < CACHE_ROWS) ? s_cache[c1 * DV + lane]
                                      : ldg_hint(&x[(size_t)(r + NWARPS) * DV + lane], pol_first);
        float d0 = v0.x * cf.x + v0.y * cf.y + v0.z * cf.z + v0.w * cf.w;
        float d1 = v1.x * cf.x + v1.y * cf.y + v1.z * cf.z + v1.w * cf.w;
#pragma unroll
        for (int o = 16; o > 0; o >>= 1) {
            d0 += __shfl_xor_sync(0xffffffffu, d0, o);
            d1 += __shfl_xor_sync(0xffffffffu, d1, o);
        }
        acc.x += v0.x * d0 + v1.x * d1;
        acc.y += v0.y * d0 + v1.y * d1;
        acc.z += v0.z * d0 + v1.z * d1;
        acc.w += v0.w * d0 + v1.w * d1;
    }
    if (r < end) {
        int ci = r - start;
        float4 v = (ci < CACHE_ROWS) ? s_cache[ci * DV + lane]
                                     : ldg_hint(&x[(size_t)r * DV + lane], pol_first);
        float d = v.x * cf.x + v.y * cf.y + v.z * cf.z + v.w * cf.w;
#pragma unroll
        for (int o = 16; o > 0; o >>= 1)
            d += __shfl_xor_sync(0xffffffffu, d, o);
        acc.x += v.x * d; acc.y += v.y * d; acc.z += v.z * d; acc.w += v.w * d;
    }
    s_partial[w][lane] = acc;
    __syncthreads();
    if (threadIdx.x < 32) {
        float4 p = s_partial[0][lane];
#pragma unroll
        for (int i = 1; i < NWARPS; i++) {
            float4 t = s_partial[i][lane];
            p.x += t.x; p.y += t.y; p.z += t.z; p.w += t.w;
        }
        p.x *= inv; p.y *= inv; p.z *= inv; p.w *= inv;
        ((float4*)g_pooled)[(size_t)b * DV + lane] = p;
    }
}

// ---------------------------------------------------------------------------
// Kernel 2: out[B,128] = pooled[B,128] @ W^T + bias.
// ---------------------------------------------------------------------------
__global__ void __launch_bounds__(128)
out_gemm_kernel(const float* __restrict__ W, const float* __restrict__ bias,
                float* __restrict__ out, int B)
{
    __shared__ float sp[TR][D];   // 16KB
    const int rb = blockIdx.x * TR;
    int rows = B - rb; if (rows > TR) rows = TR;

    const float4* src = (const float4*)(g_pooled + (size_t)rb * D);
    float4* dst = (float4*)sp;
    for (int i = threadIdx.x; i < rows * DV; i += 128) dst[i] = src[i];
    __syncthreads();

    const int j = threadIdx.x;            // output column
    float acc[TR];
    const float bj = bias[j];
#pragma unroll
    for (int r2 = 0; r2 < TR; r2++) acc[r2] = bj;

    const float4* W4  = (const float4*)(W + (size_t)j * D);
    const float4* sp4 = (const float4*)sp;
    for (int k = 0; k < DV; k++) {
        float4 wv = W4[k];
#pragma unroll
        for (int r2 = 0; r2 < TR; r2++) {
            float4 pv = sp4[r2 * DV + k];
            acc[r2] += pv.x * wv.x + pv.y * wv.y + pv.z * wv.z + pv.w * wv.w;
        }
    }
    for (int r2 = 0; r2 < rows; r2++)
        out[(size_t)(rb + r2) * D + j] = acc[r2];
}

// ---------------------------------------------------------------------------
extern "C" void kernel_launch(void* const* d_in, const int* in_sizes, int n_in,
                              void* d_out, int out_size)
{
    const float* x     = (const float*)d_in[0];
    const int*   batch = (const int*)  d_in[1];
    const float* W     = (const float*)d_in[2];
    const float* bias  = (const float*)d_in[3];
    (void)n_in;

    const int N = in_sizes[1];        // number of rows
    const int B = out_size / D;       // number of segments

    int nt = (N + 3) / 4 + 1;
    seg_bounds_scan<<<(nt + 255) / 256, 256>>>((const int4*)batch, batch, N, B);
    attention_pool_kernel<<<B, NTHREADS>>>((const float4*)x);
    out_gemm_kernel<<<(B + TR - 1) / TR, 128>>>(W, bias, (float*)d_out, B);
}